// round 15
// baseline (speedup 1.0000x reference)
#include <cuda_runtime.h>
#include <cuda_fp16.h>
#include <math.h>
#include <stdint.h>

// Problem constants
#define N_TOK   131072
#define DIM     64
#define KCODES  1024
#define TT      128
#define CH      64
#define NCH     (KCODES / CH)
#define NB      (N_TOK / TT)
#define NTHREADS 256
#define WDT_STR 68              // u32 stride per j row (272B)
#define WD_BUF  (64 * WDT_STR)

// fp16 screen error on dist: conversion ~1e-5 + accumulation (partials
// |dot|~3e-3, eps_h*|p| per add, 64 adds) worst ~6e-4 on dot -> x2 on dist
// <= ~1.3e-3 worst. MARGIN >= 2E: 3e-3.
#define MARGIN  3e-3f

#define QCAP    3072
#define SPILLCAP 1024

// smem layout (4-byte offsets)
#define OFF_XH     0                     // xh[64][68]  4352
#define OFF_WD     4352                  // wd[2][64][68]  8704
#define OFF_WSQ    13056                 // 1024
#define OFF_XSQ    14080                 // 128
#define OFF_BEST   14208                 // 128 u64  256
#define OFF_QCNT   14464
#define OFF_SCNT   14465
#define OFF_QUEUE  14468                 // 3072
#define OFF_FIDX   17540                 // 128
#define OFF_RED    17668                 // 256
#define SMEM_WORDS 17924
#define SMEM_BYTES (SMEM_WORDS * 4)      // 71696 B

// Scratch
__device__ float    g_wsq[KCODES];
__device__ int      g_counts[KCODES];
__device__ float    g_part[NB];
__device__ uint32_t g_whdT[DIM * KCODES];
__device__ uint32_t g_spill[NB * SPILLCAP];

__device__ __forceinline__ uint32_t smem_u32(const void* p) {
    uint32_t a;
    asm("{ .reg .u64 t; cvta.to.shared.u64 t, %1; cvt.u32.u64 %0, t; }"
        : "=r"(a) : "l"(p));
    return a;
}

#define CP_ASYNC16(dst_u32, src_gptr) \
    asm volatile("cp.async.ca.shared.global [%0], [%1], 16;" \
                 :: "r"(dst_u32), "l"(src_gptr) : "memory")
#define CP_COMMIT() asm volatile("cp.async.commit_group;" ::: "memory")
#define CP_WAIT0()  asm volatile("cp.async.wait_group 0;"  ::: "memory")

__device__ __forceinline__ uint32_t h2_bits(__half2 h) {
    return *reinterpret_cast<uint32_t*>(&h);
}
__device__ __forceinline__ __half2 bits_h2(uint32_t u) {
    return *reinterpret_cast<__half2*>(&u);
}

// Exact distance, R1's PROVEN accumulation (bit-matched reference argmin).
__device__ __forceinline__ float exact_dist(const float* __restrict__ xrow,
                                            const float* __restrict__ wrow,
                                            float base) {
    float dot = 0.f;
    #pragma unroll
    for (int j = 0; j < DIM; ++j)
        dot = fmaf(wrow[j], xrow[j], dot);
    return fmaf(-2.f, dot, base);
}

// Warp-aggregated candidate append: smem queue -> global spill. NEVER runs a
// divergent inline exact chain.
__device__ __forceinline__ void queue_append(
    int cond, uint32_t entry, int* qcount, int* scount, uint32_t* queue)
{
    unsigned m = __ballot_sync(0xffffffffu, cond);
    if (cond) {
        int lane   = threadIdx.x & 31;
        int leader = __ffs(m) - 1;
        int rank   = __popc(m & ((1u << lane) - 1u));
        int basep  = 0;
        if (lane == leader) basep = atomicAdd(qcount, __popc(m));
        basep = __shfl_sync(m, basep, leader);
        int slot = basep + rank;
        if (slot < QCAP) {
            queue[slot] = entry;
        } else {
            int ss = atomicAdd(scount, 1);
            if (ss < SPILLCAP)
                g_spill[(size_t)blockIdx.x * SPILLCAP + ss] = entry;
        }
    }
}

// ---------------------------------------------------------------------------
// Kernel 0: wsq + counts + duplicated/transposed fp16 codebook g_whdT[j][k]
// ---------------------------------------------------------------------------
__global__ void vq_prep(const float* __restrict__ W) {
    int k = blockIdx.x * blockDim.x + threadIdx.x;
    if (k < KCODES) {
        const float* row = W + (size_t)k * DIM;
        float s = 0.f;
        #pragma unroll
        for (int j = 0; j < DIM; ++j) {
            float v = row[j];
            s += v * v;
            __half h = __float2half_rn(v);
            g_whdT[j * KCODES + k] = h2_bits(__halves2half2(h, h));
        }
        g_wsq[k]    = s;
        g_counts[k] = 0;
    }
}

// ---------------------------------------------------------------------------
// Kernel 1: HFMA2 screen (single chain, 16 acc regs, NO reg cap) + refine
// ---------------------------------------------------------------------------
__global__ void __launch_bounds__(NTHREADS)
vq_main(const float* __restrict__ x, const float* __restrict__ W,
        float* __restrict__ out)
{
    extern __shared__ uint32_t su[];
    uint32_t* xh    = su + OFF_XH;
    uint32_t* wd    = su + OFF_WD;
    float*    wsq_s = (float*)(su + OFF_WSQ);
    float*    xsq_s = (float*)(su + OFF_XSQ);
    unsigned long long* best = (unsigned long long*)(su + OFF_BEST);
    int*      qcount = (int*)(su + OFF_QCNT);
    int*      scount = (int*)(su + OFF_SCNT);
    uint32_t* queue  = su + OFF_QUEUE;
    int*      fidx   = (int*)(su + OFF_FIDX);
    float*    red    = (float*)(su + OFF_RED);

    const int tid   = threadIdx.x;
    const int lane  = tid & 31;
    const int wid   = tid >> 5;
    const int tbase = blockIdx.x * TT;
    const int t0    = lane * 4;
    const int k0    = wid * 8;

    const uint32_t wd_u = smem_u32(wd);

    if (tid == 0) { *qcount = 0; *scount = 0; }
    if (tid < TT) best[tid] = 0xFFFFFFFFFFFFFFFFull;

    // ---- fp16 token-pair tile xh[j][tp] ----
    for (int i = tid; i < 1024; i += NTHREADS) {
        int tp = i >> 4;
        int j4 = (i & 15) << 2;
        float4 va = *(const float4*)(x + (size_t)(tbase + 2 * tp) * DIM + j4);
        float4 vb = *(const float4*)(x + (size_t)(tbase + 2 * tp + 1) * DIM + j4);
        xh[(j4 + 0) * WDT_STR + tp] = h2_bits(__floats2half2_rn(va.x, vb.x));
        xh[(j4 + 1) * WDT_STR + tp] = h2_bits(__floats2half2_rn(va.y, vb.y));
        xh[(j4 + 2) * WDT_STR + tp] = h2_bits(__floats2half2_rn(va.z, vb.z));
        xh[(j4 + 3) * WDT_STR + tp] = h2_bits(__floats2half2_rn(va.w, vb.w));
    }
    for (int i = tid; i < KCODES; i += NTHREADS) wsq_s[i] = g_wsq[i];

    // ---- prefetch W chunk 0 ----
    for (int i = tid; i < 1024; i += NTHREADS) {
        int j = i >> 4, seg = i & 15;
        CP_ASYNC16(wd_u + (uint32_t)(j * WDT_STR + seg * 4) * 4,
                   g_whdT + (size_t)j * KCODES + seg * 4);
    }
    CP_COMMIT();

    // ---- xsq per token (sequential, as R1/reference) ----
    if (tid < TT) {
        const float4* row = (const float4*)(x + (size_t)(tbase + tid) * DIM);
        float s = 0.f;
        #pragma unroll
        for (int q = 0; q < 16; ++q) {
            float4 v = row[q];
            s += v.x * v.x; s += v.y * v.y; s += v.z * v.z; s += v.w * v.w;
        }
        xsq_s[tid] = s;
    }
    __syncthreads();

    float xsqr[4];
    #pragma unroll
    for (int c = 0; c < 4; ++c) xsqr[c] = xsq_s[t0 + c];

    float rlb[4];
    #pragma unroll
    for (int c = 0; c < 4; ++c) rlb[c] = 3.0e38f;

    for (int ch = 0; ch < NCH; ++ch) {
        const int b = ch & 1;
        CP_WAIT0();
        __syncthreads();

        if (ch + 1 < NCH) {
            const uint32_t* src = g_whdT + (size_t)(ch + 1) * CH;
            const uint32_t dst0 = wd_u + (uint32_t)(((ch + 1) & 1) * WD_BUF) * 4;
            for (int i = tid; i < 1024; i += NTHREADS) {
                int j = i >> 4, seg = i & 15;
                CP_ASYNC16(dst0 + (uint32_t)(j * WDT_STR + seg * 4) * 4,
                           src + (size_t)j * KCODES + seg * 4);
            }
            CP_COMMIT();
        }

        const uint32_t* wb = wd + b * WD_BUF + k0;

        // single fp16 chain: 16 acc regs only (spill-safe)
        __half2 acc[2][8];
        #pragma unroll
        for (int p = 0; p < 2; ++p)
            #pragma unroll
            for (int k = 0; k < 8; ++k) acc[p][k] = __floats2half2_rn(0.f, 0.f);

        #pragma unroll 4
        for (int j = 0; j < DIM; ++j) {
            uint2 xv = *(const uint2*)(xh + j * WDT_STR + lane * 2);
            __half2 xp0 = bits_h2(xv.x), xp1 = bits_h2(xv.y);
            uint4 wa = *(const uint4*)(wb + j * WDT_STR);
            uint4 wc = *(const uint4*)(wb + j * WDT_STR + 4);
            acc[0][0] = __hfma2(bits_h2(wa.x), xp0, acc[0][0]);
            acc[1][0] = __hfma2(bits_h2(wa.x), xp1, acc[1][0]);
            acc[0][1] = __hfma2(bits_h2(wa.y), xp0, acc[0][1]);
            acc[1][1] = __hfma2(bits_h2(wa.y), xp1, acc[1][1]);
            acc[0][2] = __hfma2(bits_h2(wa.z), xp0, acc[0][2]);
            acc[1][2] = __hfma2(bits_h2(wa.z), xp1, acc[1][2]);
            acc[0][3] = __hfma2(bits_h2(wa.w), xp0, acc[0][3]);
            acc[1][3] = __hfma2(bits_h2(wa.w), xp1, acc[1][3]);
            acc[0][4] = __hfma2(bits_h2(wc.x), xp0, acc[0][4]);
            acc[1][4] = __hfma2(bits_h2(wc.x), xp1, acc[1][4]);
            acc[0][5] = __hfma2(bits_h2(wc.y), xp0, acc[0][5]);
            acc[1][5] = __hfma2(bits_h2(wc.y), xp1, acc[1][5]);
            acc[0][6] = __hfma2(bits_h2(wc.z), xp0, acc[0][6]);
            acc[1][6] = __hfma2(bits_h2(wc.z), xp1, acc[1][6]);
            acc[0][7] = __hfma2(bits_h2(wc.w), xp0, acc[0][7]);
            acc[1][7] = __hfma2(bits_h2(wc.w), xp1, acc[1][7]);
        }

        // ---- screen: fp32 combine, append candidates ----
        #pragma unroll
        for (int k = 0; k < 8; ++k) {
            const int lc = k0 + k;
            const int g  = ch * CH + lc;
            const float wsqk = wsq_s[g];
            float2 f0 = __half22float2(acc[0][k]);
            float2 f1 = __half22float2(acc[1][k]);
            float a0 = fmaf(-2.f, f0.x, wsqk + xsqr[0]);
            float a1 = fmaf(-2.f, f0.y, wsqk + xsqr[1]);
            float a2 = fmaf(-2.f, f1.x, wsqk + xsqr[2]);
            float a3 = fmaf(-2.f, f1.y, wsqk + xsqr[3]);
            queue_append(a0 < rlb[0] + MARGIN,
                         (uint32_t)(((t0 + 0) << 8) | lc), qcount, scount, queue);
            queue_append(a1 < rlb[1] + MARGIN,
                         (uint32_t)(((t0 + 1) << 8) | lc), qcount, scount, queue);
            queue_append(a2 < rlb[2] + MARGIN,
                         (uint32_t)(((t0 + 2) << 8) | lc), qcount, scount, queue);
            queue_append(a3 < rlb[3] + MARGIN,
                         (uint32_t)(((t0 + 3) << 8) | lc), qcount, scount, queue);
            rlb[0] = fminf(rlb[0], a0);
            rlb[1] = fminf(rlb[1], a1);
            rlb[2] = fminf(rlb[2], a2);
            rlb[3] = fminf(rlb[3], a3);
        }

        __syncthreads();

        // ---- cooperative bit-exact refine ----
        const int nq = min(*qcount, QCAP);
        const int ns = min(*scount, SPILLCAP);
        for (int i = tid; i < nq + ns; i += NTHREADS) {
            uint32_t e = (i < nq) ? queue[i]
                                  : g_spill[(size_t)blockIdx.x * SPILLCAP + (i - nq)];
            int t  = (int)(e >> 8);
            int lc = (int)(e & 255);
            int g  = ch * CH + lc;
            float base = wsq_s[g] + xsq_s[t];
            float d = exact_dist(x + (size_t)(tbase + t) * DIM,
                                 W + (size_t)g * DIM, base);
            unsigned long long key =
                ((unsigned long long)__float_as_uint(d) << 32) | (uint32_t)g;
            atomicMin(&best[t], key);
        }

        __syncthreads();
        if (tid == 0) { *qcount = 0; *scount = 0; }
    }

    __syncthreads();
    if (tid < TT) {
        int bi = (int)(best[tid] & 0xFFFFFFFFull);
        fidx[tid] = bi;
        atomicAdd(&g_counts[bi], 1);
    }
    __syncthreads();

    // ---- epilogue: quantized_st + loss partial ----
    float ls = 0.f;
    for (int i = tid; i < TT * 16; i += NTHREADS) {
        int t  = i >> 4;
        int c4 = (i & 15) << 2;
        int kb = fidx[t];
        float4 w4 = *(const float4*)(W + (size_t)kb * DIM + c4);
        float4 xv = *(const float4*)(x + (size_t)(tbase + t) * DIM + c4);
        float4 o; float dq;
        dq = w4.x - xv.x; o.x = xv.x + dq; ls = fmaf(dq, dq, ls);
        dq = w4.y - xv.y; o.y = xv.y + dq; ls = fmaf(dq, dq, ls);
        dq = w4.z - xv.z; o.z = xv.z + dq; ls = fmaf(dq, dq, ls);
        dq = w4.w - xv.w; o.w = xv.w + dq; ls = fmaf(dq, dq, ls);
        *(float4*)(out + (size_t)(tbase + t) * DIM + c4) = o;
    }

    red[tid] = ls;
    __syncthreads();
    for (int off = NTHREADS / 2; off > 0; off >>= 1) {
        if (tid < off) red[tid] += red[tid + off];
        __syncthreads();
    }
    if (tid == 0) g_part[blockIdx.x] = red[0];
}

// ---------------------------------------------------------------------------
// Kernel 2: final scalars
// ---------------------------------------------------------------------------
__global__ void vq_final(float* __restrict__ out, int out_size) {
    __shared__ float red[1024];
    __shared__ float red2[1024];
    int tid = threadIdx.x;

    red[tid] = g_part[tid];
    __syncthreads();
    for (int off = 512; off > 0; off >>= 1) {
        if (tid < off) red[tid] += red[tid + off];
        __syncthreads();
    }
    float sse = red[0];
    __syncthreads();

    int c  = g_counts[tid];
    float p = (float)c / (float)N_TOK;
    red[tid]  = p * logf(p + 1e-10f);
    red2[tid] = (c >= 1) ? 1.f : 0.f;
    __syncthreads();
    for (int off = 512; off > 0; off >>= 1) {
        if (tid < off) { red[tid] += red[tid + off]; red2[tid] += red2[tid + off]; }
        __syncthreads();
    }
    if (tid == 0 && out_size >= N_TOK * DIM + 3) {
        float mse = sse / (float)(N_TOK * DIM);
        out[N_TOK * DIM + 0] = mse + 2.0f * mse;
        out[N_TOK * DIM + 1] = expf(-red[0]);
        out[N_TOK * DIM + 2] = red2[0];
    }
}

// ---------------------------------------------------------------------------
extern "C" void kernel_launch(void* const* d_in, const int* in_sizes, int n_in,
                              void* d_out, int out_size) {
    const float* x = (const float*)d_in[0];
    const float* W = (const float*)d_in[1];
    float* out = (float*)d_out;

    cudaFuncSetAttribute(vq_main, cudaFuncAttributeMaxDynamicSharedMemorySize,
                         SMEM_BYTES);

    vq_prep<<<4, 256>>>(W);
    vq_main<<<NB, NTHREADS, SMEM_BYTES>>>(x, W, out);
    vq_final<<<1, 1024>>>(out, out_size);
}

// round 16
// speedup vs baseline: 5.0278x; 5.0278x over previous
#include <cuda_runtime.h>
#include <math.h>
#include <stdint.h>

// Problem constants
#define N_TOK   131072      // 32 * 4096 tokens
#define DIM     64
#define KCODES  1024
#define TT      64          // tokens per CTA (halved vs R10: wave quantization)
#define CK      64          // codes per chunk
#define NCHUNK  (KCODES / CK)   // 16
#define NB      (N_TOK / TT)    // 2048 CTAs
#define NTHREADS 256
#define WT_STR  68          // padded k-stride of transposed W tile

// smem float offsets
#define OFF_XS   0          // xs[64][64] transposed x tile    : 4096
#define OFF_WT   4096       // wsT[2][64][68] transposed W     : 8704
#define OFF_XSQ  12800      // xsq[64]                         : 64
#define SMEM_FLOATS 12864
#define SMEM_BYTES (SMEM_FLOATS * 4)     // 51456 B -> 4 CTAs/SM

// Scratch
__device__ float g_wsq[KCODES];
__device__ int   g_counts[KCODES];
__device__ float g_part[NB];

// ---- packed f32x2 helpers (proven real FFMA2 HW in R10) ----
__device__ __forceinline__ void fma2(unsigned long long& acc,
                                     unsigned long long w2,
                                     unsigned long long x2) {
    asm("fma.rn.f32x2 %0, %1, %2, %0;" : "+l"(acc) : "l"(w2), "l"(x2));
}
__device__ __forceinline__ unsigned long long dup2(float v) {
    unsigned long long r;
    asm("mov.b64 %0, {%1, %1};" : "=l"(r) : "f"(v));
    return r;
}
__device__ __forceinline__ void unpack2(unsigned long long a, float& lo, float& hi) {
    asm("mov.b64 {%0, %1}, %2;" : "=f"(lo), "=f"(hi) : "l"(a));
}

// ---------------------------------------------------------------------------
// Kernel 0: wsq[k] = sum_j W[k][j]^2 (sequential), zero counts
// ---------------------------------------------------------------------------
__global__ void vq_prep(const float* __restrict__ W) {
    int k = blockIdx.x * blockDim.x + threadIdx.x;
    if (k < KCODES) {
        const float* row = W + (size_t)k * DIM;
        float s = 0.f;
        #pragma unroll
        for (int j = 0; j < DIM; ++j) s += row[j] * row[j];
        g_wsq[k]    = s;
        g_counts[k] = 0;
    }
}

// ---------------------------------------------------------------------------
// Kernel 1: packed-f32x2 GEMM (R10 engine, TT=64 / 4 CTAs/SM)
//   256 thr (8 warps). Tokens on lanes (2/thread), codes on warps (8/warp,
//   4 packed pairs). W chunk transposed in smem. Bit-identical math to R10/R1.
// ---------------------------------------------------------------------------
__global__ void __launch_bounds__(NTHREADS)
vq_main(const float* __restrict__ x, const float* __restrict__ W,
        float* __restrict__ out)
{
    extern __shared__ float sf[];
    float* xs  = sf + OFF_XS;                 // [j][t]
    float* wsT = sf + OFF_WT;                 // [2][j][k] padded
    float* xsq = sf + OFF_XSQ;
    // union region inside wsT (valid after mainloop):
    float* bd   = wsT;                        // [8][64]  = 512
    int*   bi   = (int*)(wsT + 512);          // [8][64]  = 512
    int*   fidx = (int*)(wsT + 1024);         // [64]
    float* red  = wsT;                        // loss reduce [256] (bd dead)

    const int tid  = threadIdx.x;
    const int wid  = tid >> 5;
    const int lane = tid & 31;
    const int tbase = blockIdx.x * TT;
    const int t0 = lane * 2;                  // this thread's 2 tokens
    const int k0 = wid * 8;                   // this warp's 8 codes (4 pairs)

    // ---- load x tile transposed ----
    for (int i = tid; i < TT * 16; i += NTHREADS) {
        int t  = i >> 4;
        int j4 = (i & 15) << 2;
        float4 v = *(const float4*)(x + (size_t)(tbase + t) * DIM + j4);
        xs[(j4 + 0) * TT + t] = v.x;
        xs[(j4 + 1) * TT + t] = v.y;
        xs[(j4 + 2) * TT + t] = v.z;
        xs[(j4 + 3) * TT + t] = v.w;
    }
    // ---- load W chunk 0 transposed into buffer 0 ----
    for (int i = tid; i < CK * 16; i += NTHREADS) {
        int r = i >> 4, c4 = (i & 15) << 2;
        float4 v = *(const float4*)(W + (size_t)r * DIM + c4);
        wsT[(c4 + 0) * WT_STR + r] = v.x;
        wsT[(c4 + 1) * WT_STR + r] = v.y;
        wsT[(c4 + 2) * WT_STR + r] = v.z;
        wsT[(c4 + 3) * WT_STR + r] = v.w;
    }
    __syncthreads();

    // ---- xsq per token (sequential j, as reference/R1) ----
    if (tid < TT) {
        float s = 0.f;
        for (int j = 0; j < DIM; ++j) { float v = xs[j * TT + tid]; s += v * v; }
        xsq[tid] = s;
    }
    __syncthreads();
    float xsqr[2];
    #pragma unroll
    for (int c = 0; c < 2; ++c) xsqr[c] = xsq[t0 + c];

    float bestd[2]; int besti[2];
    #pragma unroll
    for (int c = 0; c < 2; ++c) { bestd[c] = 3.0e38f; besti[c] = 0; }

    for (int ch = 0; ch < NCHUNK; ++ch) {
        const int b = ch & 1;

        // register-prefetch next chunk (latency hidden behind compute)
        float4 pf[4];
        if (ch + 1 < NCHUNK) {
            const float* src = W + (size_t)(ch + 1) * CK * DIM;
            #pragma unroll
            for (int q = 0; q < 4; ++q) {
                int i = tid + q * NTHREADS;
                int r = i >> 4, c4 = (i & 15) << 2;
                pf[q] = *(const float4*)(src + (size_t)r * DIM + c4);
            }
        }

        const float* wb = wsT + b * (CK * WT_STR) + k0;

        unsigned long long acc[2][4];     // [token][code-pair]
        #pragma unroll
        for (int c = 0; c < 2; ++c)
            #pragma unroll
            for (int p = 0; p < 4; ++p) acc[c][p] = 0ull;

        #pragma unroll 4
        for (int j = 0; j < DIM; ++j) {
            float2 xq = *(const float2*)(xs + j * TT + t0);
            const ulonglong2* wp = (const ulonglong2*)(wb + j * WT_STR);
            ulonglong2 wA = wp[0];        // code pairs 0,1 (broadcast)
            ulonglong2 wB = wp[1];        // code pairs 2,3
            unsigned long long xx;
            xx = dup2(xq.x);
            fma2(acc[0][0], wA.x, xx); fma2(acc[0][1], wA.y, xx);
            fma2(acc[0][2], wB.x, xx); fma2(acc[0][3], wB.y, xx);
            xx = dup2(xq.y);
            fma2(acc[1][0], wA.x, xx); fma2(acc[1][1], wA.y, xx);
            fma2(acc[1][2], wB.x, xx); fma2(acc[1][3], wB.y, xx);
        }

        // distances + running argmin (codes ascending -> lowest-index ties)
        const int kg0 = ch * CK + k0;
        #pragma unroll
        for (int p = 0; p < 4; ++p) {
            float wlo = g_wsq[kg0 + 2 * p];
            float whi = g_wsq[kg0 + 2 * p + 1];
            #pragma unroll
            for (int c = 0; c < 2; ++c) {
                float lo, hi;
                unpack2(acc[c][p], lo, hi);
                float d;
                d = fmaf(-2.f, lo, wlo + xsqr[c]);
                if (d < bestd[c]) { bestd[c] = d; besti[c] = kg0 + 2 * p; }
                d = fmaf(-2.f, hi, whi + xsqr[c]);
                if (d < bestd[c]) { bestd[c] = d; besti[c] = kg0 + 2 * p + 1; }
            }
        }

        // store prefetched chunk into other buffer (transposed)
        if (ch + 1 < NCHUNK) {
            float* dst = wsT + (b ^ 1) * (CK * WT_STR);
            #pragma unroll
            for (int q = 0; q < 4; ++q) {
                int i = tid + q * NTHREADS;
                int r = i >> 4, c4 = (i & 15) << 2;
                dst[(c4 + 0) * WT_STR + r] = pf[q].x;
                dst[(c4 + 1) * WT_STR + r] = pf[q].y;
                dst[(c4 + 2) * WT_STR + r] = pf[q].z;
                dst[(c4 + 3) * WT_STR + r] = pf[q].w;
            }
        }
        __syncthreads();
    }

    // ---- cross-warp argmin reduction (wsT region now reusable) ----
    #pragma unroll
    for (int c = 0; c < 2; ++c) {
        bd[wid * TT + t0 + c] = bestd[c];
        bi[wid * TT + t0 + c] = besti[c];
    }
    __syncthreads();
    if (tid < TT) {
        float bdv = bd[tid]; int biv = bi[tid];
        #pragma unroll
        for (int w = 1; w < 8; ++w) {
            float d2 = bd[w * TT + tid]; int i2 = bi[w * TT + tid];
            if (d2 < bdv || (d2 == bdv && i2 < biv)) { bdv = d2; biv = i2; }
        }
        fidx[tid] = biv;
        atomicAdd(&g_counts[biv], 1);
    }
    __syncthreads();

    // ---- epilogue: quantized_st + loss partial (as R1/R10) ----
    float ls = 0.f;
    for (int s = tid; s < TT * 2; s += NTHREADS) {   // 32-float segments
        int t  = s >> 1;
        int j0 = (s & 1) * 32;
        int kb = fidx[t];
        const float* wrow = W + (size_t)kb * DIM + j0;
        float* orow = out + (size_t)(tbase + t) * DIM + j0;
        #pragma unroll
        for (int jj = 0; jj < 32; jj += 4) {
            float4 w4 = *(const float4*)(wrow + jj);
            float4 o;
            float xv, dq;
            xv = xs[(j0 + jj + 0) * TT + t]; dq = w4.x - xv; o.x = xv + dq; ls = fmaf(dq, dq, ls);
            xv = xs[(j0 + jj + 1) * TT + t]; dq = w4.y - xv; o.y = xv + dq; ls = fmaf(dq, dq, ls);
            xv = xs[(j0 + jj + 2) * TT + t]; dq = w4.z - xv; o.z = xv + dq; ls = fmaf(dq, dq, ls);
            xv = xs[(j0 + jj + 3) * TT + t]; dq = w4.w - xv; o.w = xv + dq; ls = fmaf(dq, dq, ls);
            *(float4*)(orow + jj) = o;
        }
    }

    __syncthreads();
    red[tid] = ls;
    __syncthreads();
    for (int off = NTHREADS / 2; off > 0; off >>= 1) {
        if (tid < off) red[tid] += red[tid + off];
        __syncthreads();
    }
    if (tid == 0) g_part[blockIdx.x] = red[0];
}

// ---------------------------------------------------------------------------
// Kernel 2: final scalars (loss, perplexity, usage); NB=2048 partials
// ---------------------------------------------------------------------------
__global__ void vq_final(float* __restrict__ out, int out_size) {
    __shared__ float red[1024];
    __shared__ float red2[1024];
    int tid = threadIdx.x;

    red[tid] = g_part[tid] + g_part[tid + 1024];
    __syncthreads();
    for (int off = 512; off > 0; off >>= 1) {
        if (tid < off) red[tid] += red[tid + off];
        __syncthreads();
    }
    float sse = red[0];
    __syncthreads();

    int c  = g_counts[tid];
    float p = (float)c / (float)N_TOK;
    red[tid]  = p * logf(p + 1e-10f);
    red2[tid] = (c >= 1) ? 1.f : 0.f;
    __syncthreads();
    for (int off = 512; off > 0; off >>= 1) {
        if (tid < off) { red[tid] += red[tid + off]; red2[tid] += red2[tid + off]; }
        __syncthreads();
    }
    if (tid == 0 && out_size >= N_TOK * DIM + 3) {
        float mse = sse / (float)(N_TOK * DIM);
        out[N_TOK * DIM + 0] = mse + 2.0f * mse;   // q_latent + COMMITMENT_COST*e_latent
        out[N_TOK * DIM + 1] = expf(-red[0]);
        out[N_TOK * DIM + 2] = red2[0];
    }
}

// ---------------------------------------------------------------------------
extern "C" void kernel_launch(void* const* d_in, const int* in_sizes, int n_in,
                              void* d_out, int out_size) {
    const float* x = (const float*)d_in[0];   // [32,4096,64] f32
    const float* W = (const float*)d_in[1];   // [1024,64] f32
    float* out = (float*)d_out;

    cudaFuncSetAttribute(vq_main, cudaFuncAttributeMaxDynamicSharedMemorySize,
                         SMEM_BYTES);

    vq_prep<<<8, 128>>>(W);
    vq_main<<<NB, NTHREADS, SMEM_BYTES>>>(x, W, out);
    vq_final<<<1, 1024>>>(out, out_size);
}

// round 17
// speedup vs baseline: 6.7167x; 1.3359x over previous
#include <cuda_runtime.h>
#include <math.h>
#include <stdint.h>

// Problem constants
#define N_TOK   131072      // 32 * 4096 tokens
#define DIM     64
#define KCODES  1024
#define TT      128         // tokens per CTA (R10-proven)
#define CK      64          // codes per chunk
#define NCHUNK  (KCODES / CK)   // 16
#define NB      (N_TOK / TT)    // 1024 CTAs
#define NTHREADS 256
#define WT_STR  68          // padded k-stride of transposed W tile

// smem float offsets
#define OFF_XS   0          // xs[64][128] transposed x tile   : 8192
#define OFF_WT   8192       // wsT[2][64][68] transposed W     : 8704
#define OFF_WSQ  16896      // wsq_s[1024]                     : 1024
#define OFF_XSQ  17920      // xsq[128]                        : 128
#define SMEM_FLOATS 18048
#define SMEM_BYTES (SMEM_FLOATS * 4)   // 72192 B -> 3 CTAs/SM

// Scratch
__device__ float g_wsq[KCODES];
__device__ int   g_counts[KCODES];
__device__ float g_part[NB];

// ---- packed f32x2 helpers (proven real FFMA2 HW in R10) ----
__device__ __forceinline__ void fma2(unsigned long long& acc,
                                     unsigned long long w2,
                                     unsigned long long x2) {
    asm("fma.rn.f32x2 %0, %1, %2, %0;" : "+l"(acc) : "l"(w2), "l"(x2));
}
__device__ __forceinline__ unsigned long long dup2(float v) {
    unsigned long long r;
    asm("mov.b64 %0, {%1, %1};" : "=l"(r) : "f"(v));
    return r;
}
__device__ __forceinline__ void unpack2(unsigned long long a, float& lo, float& hi) {
    asm("mov.b64 {%0, %1}, %2;" : "=f"(lo), "=f"(hi) : "l"(a));
}

// ---------------------------------------------------------------------------
// Kernel 0: wsq[k] = sum_j W[k][j]^2 (sequential), zero counts
// ---------------------------------------------------------------------------
__global__ void vq_prep(const float* __restrict__ W) {
    int k = blockIdx.x * blockDim.x + threadIdx.x;
    if (k < KCODES) {
        const float* row = W + (size_t)k * DIM;
        float s = 0.f;
        #pragma unroll
        for (int j = 0; j < DIM; ++j) s += row[j] * row[j];
        g_wsq[k]    = s;
        g_counts[k] = 0;
    }
}

// ---------------------------------------------------------------------------
// Kernel 1: packed-f32x2 distance GEMM + argmin + quantize + loss + counts
//   R10 mainloop verbatim (FMA2 bank-limited floor) + wsq staged in smem.
//   256 thr (8 warps). Tokens on lanes (4/thread), codes on warps (8/warp,
//   4 packed pairs). W chunk transposed in smem, double-buffered via regs.
// ---------------------------------------------------------------------------
__global__ void __launch_bounds__(NTHREADS, 2)
vq_main(const float* __restrict__ x, const float* __restrict__ W,
        float* __restrict__ out)
{
    extern __shared__ float sf[];
    float* xs    = sf + OFF_XS;               // [j][t]
    float* wsT   = sf + OFF_WT;               // [2][j][k] padded
    float* wsq_s = sf + OFF_WSQ;              // [1024]
    float* xsq   = sf + OFF_XSQ;
    // union region inside wsT (valid after mainloop's final __syncthreads):
    float* bd   = wsT;                        // [8][128]
    int*   bi   = (int*)(wsT + 1024);         // [8][128]
    int*   fidx = (int*)(wsT + 2048);         // [128]
    float* red  = wsT;                        // loss reduce (after argmin)

    const int tid  = threadIdx.x;
    const int wid  = tid >> 5;
    const int lane = tid & 31;
    const int tbase = blockIdx.x * TT;
    const int t0 = lane * 4;                  // this thread's 4 tokens
    const int k0 = wid * 8;                   // this warp's 8 codes (4 pairs)

    // ---- load x tile transposed ----
    for (int i = tid; i < TT * 16; i += NTHREADS) {
        int t  = i >> 4;
        int j4 = (i & 15) << 2;
        float4 v = *(const float4*)(x + (size_t)(tbase + t) * DIM + j4);
        xs[(j4 + 0) * TT + t] = v.x;
        xs[(j4 + 1) * TT + t] = v.y;
        xs[(j4 + 2) * TT + t] = v.z;
        xs[(j4 + 3) * TT + t] = v.w;
    }
    // ---- stage wsq in smem (R17: removes 128 LDG/thread from argmin path) ----
    for (int i = tid; i < KCODES; i += NTHREADS) wsq_s[i] = g_wsq[i];
    // ---- load W chunk 0 transposed into buffer 0 ----
    for (int i = tid; i < CK * 16; i += NTHREADS) {
        int r = i >> 4, c4 = (i & 15) << 2;
        float4 v = *(const float4*)(W + (size_t)r * DIM + c4);
        wsT[(c4 + 0) * WT_STR + r] = v.x;
        wsT[(c4 + 1) * WT_STR + r] = v.y;
        wsT[(c4 + 2) * WT_STR + r] = v.z;
        wsT[(c4 + 3) * WT_STR + r] = v.w;
    }
    __syncthreads();

    // ---- xsq per token (sequential j, as reference/R1) ----
    if (tid < TT) {
        float s = 0.f;
        for (int j = 0; j < DIM; ++j) { float v = xs[j * TT + tid]; s += v * v; }
        xsq[tid] = s;
    }
    __syncthreads();
    float xsqr[4];
    #pragma unroll
    for (int c = 0; c < 4; ++c) xsqr[c] = xsq[t0 + c];

    float bestd[4]; int besti[4];
    #pragma unroll
    for (int c = 0; c < 4; ++c) { bestd[c] = 3.0e38f; besti[c] = 0; }

    for (int ch = 0; ch < NCHUNK; ++ch) {
        const int b = ch & 1;

        // register-prefetch next chunk (latency hidden behind compute)
        float4 pf[4];
        if (ch + 1 < NCHUNK) {
            const float* src = W + (size_t)(ch + 1) * CK * DIM;
            #pragma unroll
            for (int q = 0; q < 4; ++q) {
                int i = tid + q * NTHREADS;
                int r = i >> 4, c4 = (i & 15) << 2;
                pf[q] = *(const float4*)(src + (size_t)r * DIM + c4);
            }
        }

        const float* wb = wsT + b * (CK * WT_STR) + k0;

        unsigned long long acc[4][4];     // [token][code-pair]
        #pragma unroll
        for (int c = 0; c < 4; ++c)
            #pragma unroll
            for (int p = 0; p < 4; ++p) acc[c][p] = 0ull;

        #pragma unroll 4
        for (int j = 0; j < DIM; ++j) {
            float4 xq = *(const float4*)(xs + j * TT + t0);
            const ulonglong2* wp = (const ulonglong2*)(wb + j * WT_STR);
            ulonglong2 wA = wp[0];        // code pairs 0,1 (broadcast)
            ulonglong2 wB = wp[1];        // code pairs 2,3
            unsigned long long xx;
            xx = dup2(xq.x);
            fma2(acc[0][0], wA.x, xx); fma2(acc[0][1], wA.y, xx);
            fma2(acc[0][2], wB.x, xx); fma2(acc[0][3], wB.y, xx);
            xx = dup2(xq.y);
            fma2(acc[1][0], wA.x, xx); fma2(acc[1][1], wA.y, xx);
            fma2(acc[1][2], wB.x, xx); fma2(acc[1][3], wB.y, xx);
            xx = dup2(xq.z);
            fma2(acc[2][0], wA.x, xx); fma2(acc[2][1], wA.y, xx);
            fma2(acc[2][2], wB.x, xx); fma2(acc[2][3], wB.y, xx);
            xx = dup2(xq.w);
            fma2(acc[3][0], wA.x, xx); fma2(acc[3][1], wA.y, xx);
            fma2(acc[3][2], wB.x, xx); fma2(acc[3][3], wB.y, xx);
        }

        // distances + running argmin (codes ascending -> lowest-index ties)
        const int kg0 = ch * CK + k0;
        #pragma unroll
        for (int p = 0; p < 4; ++p) {
            float wlo = wsq_s[kg0 + 2 * p];
            float whi = wsq_s[kg0 + 2 * p + 1];
            #pragma unroll
            for (int c = 0; c < 4; ++c) {
                float lo, hi;
                unpack2(acc[c][p], lo, hi);
                float d;
                d = fmaf(-2.f, lo, wlo + xsqr[c]);
                if (d < bestd[c]) { bestd[c] = d; besti[c] = kg0 + 2 * p; }
                d = fmaf(-2.f, hi, whi + xsqr[c]);
                if (d < bestd[c]) { bestd[c] = d; besti[c] = kg0 + 2 * p + 1; }
            }
        }

        // store prefetched chunk into other buffer (transposed)
        if (ch + 1 < NCHUNK) {
            float* dst = wsT + (b ^ 1) * (CK * WT_STR);
            #pragma unroll
            for (int q = 0; q < 4; ++q) {
                int i = tid + q * NTHREADS;
                int r = i >> 4, c4 = (i & 15) << 2;
                dst[(c4 + 0) * WT_STR + r] = pf[q].x;
                dst[(c4 + 1) * WT_STR + r] = pf[q].y;
                dst[(c4 + 2) * WT_STR + r] = pf[q].z;
                dst[(c4 + 3) * WT_STR + r] = pf[q].w;
            }
        }
        __syncthreads();
    }

    // ---- cross-warp argmin reduction (exact dists, index tie-break) ----
    #pragma unroll
    for (int c = 0; c < 4; ++c) {
        bd[wid * TT + t0 + c] = bestd[c];
        bi[wid * TT + t0 + c] = besti[c];
    }
    __syncthreads();
    if (tid < TT) {
        float bdv = bd[tid]; int biv = bi[tid];
        #pragma unroll
        for (int w = 1; w < 8; ++w) {
            float d2 = bd[w * TT + tid]; int i2 = bi[w * TT + tid];
            if (d2 < bdv || (d2 == bdv && i2 < biv)) { bdv = d2; biv = i2; }
        }
        fidx[tid] = biv;
        atomicAdd(&g_counts[biv], 1);
    }
    __syncthreads();

    // ---- epilogue: quantized_st + loss partial (as R1/R10) ----
    float ls = 0.f;
    for (int s = tid; s < TT * 2; s += NTHREADS) {
        int t  = s >> 1;
        int j0 = (s & 1) * 32;
        int kb = fidx[t];
        const float* wrow = W + (size_t)kb * DIM + j0;
        float* orow = out + (size_t)(tbase + t) * DIM + j0;
        #pragma unroll
        for (int jj = 0; jj < 32; jj += 4) {
            float4 w4 = *(const float4*)(wrow + jj);
            float4 o;
            float xv, dq;
            xv = xs[(j0 + jj + 0) * TT + t]; dq = w4.x - xv; o.x = xv + dq; ls = fmaf(dq, dq, ls);
            xv = xs[(j0 + jj + 1) * TT + t]; dq = w4.y - xv; o.y = xv + dq; ls = fmaf(dq, dq, ls);
            xv = xs[(j0 + jj + 2) * TT + t]; dq = w4.z - xv; o.z = xv + dq; ls = fmaf(dq, dq, ls);
            xv = xs[(j0 + jj + 3) * TT + t]; dq = w4.w - xv; o.w = xv + dq; ls = fmaf(dq, dq, ls);
            *(float4*)(orow + jj) = o;
        }
    }

    __syncthreads();
    red[tid] = ls;
    __syncthreads();
    for (int off = NTHREADS / 2; off > 0; off >>= 1) {
        if (tid < off) red[tid] += red[tid + off];
        __syncthreads();
    }
    if (tid == 0) g_part[blockIdx.x] = red[0];
}

// ---------------------------------------------------------------------------
// Kernel 2: final scalars (loss, perplexity, usage)
// ---------------------------------------------------------------------------
__global__ void vq_final(float* __restrict__ out, int out_size) {
    __shared__ float red[1024];
    __shared__ float red2[1024];
    int tid = threadIdx.x;

    red[tid] = g_part[tid];
    __syncthreads();
    for (int off = 512; off > 0; off >>= 1) {
        if (tid < off) red[tid] += red[tid + off];
        __syncthreads();
    }
    float sse = red[0];
    __syncthreads();

    int c  = g_counts[tid];
    float p = (float)c / (float)N_TOK;
    red[tid]  = p * logf(p + 1e-10f);
    red2[tid] = (c >= 1) ? 1.f : 0.f;
    __syncthreads();
    for (int off = 512; off > 0; off >>= 1) {
        if (tid < off) { red[tid] += red[tid + off]; red2[tid] += red2[tid + off]; }
        __syncthreads();
    }
    if (tid == 0 && out_size >= N_TOK * DIM + 3) {
        float mse = sse / (float)(N_TOK * DIM);
        out[N_TOK * DIM + 0] = mse + 2.0f * mse;   // q_latent + COMMITMENT_COST*e_latent
        out[N_TOK * DIM + 1] = expf(-red[0]);
        out[N_TOK * DIM + 2] = red2[0];
    }
}

// ---------------------------------------------------------------------------
extern "C" void kernel_launch(void* const* d_in, const int* in_sizes, int n_in,
                              void* d_out, int out_size) {
    const float* x = (const float*)d_in[0];   // [32,4096,64] f32
    const float* W = (const float*)d_in[1];   // [1024,64] f32
    float* out = (float*)d_out;

    cudaFuncSetAttribute(vq_main, cudaFuncAttributeMaxDynamicSharedMemorySize,
                         SMEM_BYTES);

    vq_prep<<<8, 128>>>(W);
    vq_main<<<NB, NTHREADS, SMEM_BYTES>>>(x, W, out);
    vq_final<<<1, 1024>>>(out, out_size);
}